// round 1
// baseline (speedup 1.0000x reference)
#include <cuda_runtime.h>
#include <cstdint>

// Problem constants
#define Bn 4096
#define Vn 256
#define Hn 64
#define SROW (257 * 256)   // stride of one batch element in `state`

// K1 tiling
#define TM   128           // rows (b,v) per CTA
#define KC   32            // K chunk
#define APAD 130           // padded row stride for A tile (conflict control + 8B align)

// Column-softmax scratch (device globals: no allocation APIs allowed)
__device__ float g_pm[64 * Vn];
__device__ float g_ps[64 * Vn];
__device__ float g_colM[Vn];
__device__ float g_colS[Vn];

// ---------------------------------------------------------------------------
// Packed f32x2 FMA (FFMA2): 2 FMAs per instruction. FFMA-3reg is rt=2 on
// sm_103a, so this doubles SIMT fp32 throughput (SASS_QUICKREF: "FFMA2 from
// C++ only via PTX fma.rn.f32x2").
// ---------------------------------------------------------------------------
__device__ __forceinline__ void ffma2(unsigned long long& c,
                                      unsigned long long a,
                                      unsigned long long b) {
    asm volatile("fma.rn.f32x2 %0, %1, %2, %0;" : "+l"(c) : "l"(a), "l"(b));
}
__device__ __forceinline__ unsigned long long dup2(float x) {
    unsigned long long r;
    asm("mov.b64 %0, {%1, %1};" : "=l"(r) : "r"(__float_as_uint(x)));
    return r;
}

// ---------------------------------------------------------------------------
// K1: fused GEMM + epilogue.
//   For each row r=(b,v):  q[r] = sum_h relu( dist[b,v,:]·W1[:,h] + vis*b_vis[h] ) * w2[h]
// M = 1,048,576, N = 64, K = 256.  One CTA = 128 rows x 64 h, all within one b.
// Thread (tr=tid>>4, tc=tid&15): 4 row-PAIRS (f32x2 packed) x 4 h columns.
// ---------------------------------------------------------------------------
__global__ __launch_bounds__(256) void k1_gemm(
    const float* __restrict__ state, const float* __restrict__ W1,
    const float* __restrict__ b_vis, const float* __restrict__ w2,
    float* __restrict__ qout)
{
    __shared__ float As[KC * APAD];   // A tile, layout [k][row], pad 130
    __shared__ float Bs[KC * Hn];     // W1 chunk, layout [k][h]

    const int tid = threadIdx.x;
    const int tc  = tid & 15;         // h-group (4 h each)
    const int tr  = tid >> 4;         // row-group (row pairs)
    const int rowBase = blockIdx.x * TM;
    const int b     = rowBase >> 8;
    const int vBase = rowBase & 255;

    // A global-load mapping: 256 threads sweep 128 rows x 32 k per chunk,
    // 4 float4 per thread, coalesced 128B per 8 lanes.
    const int lr = tid >> 3;          // 0..31 (row within sweep)
    const int kv = tid & 7;           // 0..7  (float4 within k-chunk)
    const float* aPtr = state + (size_t)b * SROW + (size_t)(vBase + lr + 1) * 256 + kv * 4;

    unsigned long long acc[4][4];
    #pragma unroll
    for (int p = 0; p < 4; p++)
        #pragma unroll
        for (int j = 0; j < 4; j++) acc[p][j] = 0ull;

    float4 aHold[4];
    float4 bHold[2];

    // prologue: chunk 0 -> regs
    #pragma unroll
    for (int i = 0; i < 4; i++)
        aHold[i] = *(const float4*)(aPtr + (size_t)i * 32 * 256);
    #pragma unroll
    for (int i = 0; i < 2; i++)
        bHold[i] = ((const float4*)W1)[tid + i * 256];

    const int rb0 = tr * 2;

    #pragma unroll 1
    for (int c = 0; c < 8; c++) {
        // regs -> smem
        #pragma unroll
        for (int i = 0; i < 4; i++) {
            const float4 v = aHold[i];
            const int r = lr + i * 32;
            As[(kv * 4 + 0) * APAD + r] = v.x;
            As[(kv * 4 + 1) * APAD + r] = v.y;
            As[(kv * 4 + 2) * APAD + r] = v.z;
            As[(kv * 4 + 3) * APAD + r] = v.w;
        }
        #pragma unroll
        for (int i = 0; i < 2; i++)
            ((float4*)Bs)[tid + i * 256] = bHold[i];
        __syncthreads();

        // issue next chunk's global loads early (overlap with compute)
        if (c < 7) {
            #pragma unroll
            for (int i = 0; i < 4; i++)
                aHold[i] = *(const float4*)(aPtr + (c + 1) * 32 + (size_t)i * 32 * 256);
            #pragma unroll
            for (int i = 0; i < 2; i++)
                bHold[i] = ((const float4*)W1)[(c + 1) * 512 + tid + i * 256];
        }

        // compute: per k-step 4x LDS.64 (A pairs) + 1x LDS.128 (B) + 4 dups + 16 FFMA2
        #pragma unroll 8
        for (int kk = 0; kk < KC; kk++) {
            const float4 bq = ((const float4*)Bs)[kk * 16 + tc];
            const unsigned long long bb0 = dup2(bq.x);
            const unsigned long long bb1 = dup2(bq.y);
            const unsigned long long bb2 = dup2(bq.z);
            const unsigned long long bb3 = dup2(bq.w);
            #pragma unroll
            for (int p = 0; p < 4; p++) {
                const unsigned long long aa =
                    *(const unsigned long long*)(As + kk * APAD + rb0 + p * 32);
                ffma2(acc[p][0], aa, bb0);
                ffma2(acc[p][1], aa, bb1);
                ffma2(acc[p][2], aa, bb2);
                ffma2(acc[p][3], aa, bb3);
            }
        }
        __syncthreads();
    }

    // ---- epilogue: bias + relu + dot(w2), reduce over h across the 16-lane group ----
    const int h0 = tc * 4;
    const float4 bv4 = *(const float4*)(b_vis + h0);
    const float4 w24 = *(const float4*)(w2 + h0);
    const float bvv[4] = {bv4.x, bv4.y, bv4.z, bv4.w};
    const float ww[4]  = {w24.x, w24.y, w24.z, w24.w};
    const float* visRow = state + (size_t)b * SROW;   // visited = state[b,0,:]

    #pragma unroll
    for (int p = 0; p < 4; p++) {
        const int r0 = rb0 + p * 32;
        const float vis0 = visRow[vBase + r0];
        const float vis1 = visRow[vBase + r0 + 1];
        float q0 = 0.f, q1 = 0.f;
        #pragma unroll
        for (int j = 0; j < 4; j++) {
            const float2 cc = *reinterpret_cast<const float2*>(&acc[p][j]);
            q0 += fmaxf(fmaf(vis0, bvv[j], cc.x), 0.f) * ww[j];
            q1 += fmaxf(fmaf(vis1, bvv[j], cc.y), 0.f) * ww[j];
        }
        // reduce across the 16 threads sharing this row set (lanes xor 8,4,2,1)
        #pragma unroll
        for (int off = 8; off >= 1; off >>= 1) {
            q0 += __shfl_xor_sync(0xffffffffu, q0, off);
            q1 += __shfl_xor_sync(0xffffffffu, q1, off);
        }
        if (tc == 0) {
            qout[rowBase + r0]     = q0;
            qout[rowBase + r0 + 1] = q1;
        }
    }
}

// ---------------------------------------------------------------------------
// K2: column-wise (axis=0!) softmax stats, online, 64-row slabs per CTA.
// ---------------------------------------------------------------------------
__global__ __launch_bounds__(256) void k2_colpart(const float* __restrict__ q)
{
    const int t  = threadIdx.x;
    const int r0 = blockIdx.x * 64;
    float m = -3.402823466e38f, s = 0.f;
    const float* p = q + (size_t)r0 * Vn + t;
    #pragma unroll 4
    for (int i = 0; i < 64; i++) {
        const float x  = p[(size_t)i * Vn];
        const float nm = fmaxf(m, x);
        s = s * __expf(m - nm) + __expf(x - nm);
        m = nm;
    }
    g_pm[blockIdx.x * Vn + t] = m;
    g_ps[blockIdx.x * Vn + t] = s;
}

__global__ __launch_bounds__(256) void k2_colcomb()
{
    const int t = threadIdx.x;
    float M = -3.402823466e38f;
    #pragma unroll 8
    for (int i = 0; i < 64; i++) M = fmaxf(M, g_pm[i * Vn + t]);
    float S = 0.f;
    #pragma unroll 8
    for (int i = 0; i < 64; i++) S += g_ps[i * Vn + t] * __expf(g_pm[i * Vn + t] - M);
    g_colM[t] = M;
    g_colS[t] = S;
}

// ---------------------------------------------------------------------------
// K3: temp = softmax0(q)+0.01, mask visited==0, row-normalize (onehot fallback),
// plus value[b] = q[b,:]·Wv + bv.  One CTA per b.
// ---------------------------------------------------------------------------
__global__ __launch_bounds__(256) void k3_final(
    const float* __restrict__ q, const float* __restrict__ state,
    const float* __restrict__ Wv, const float* __restrict__ bv,
    float* __restrict__ policy, float* __restrict__ value)
{
    __shared__ float sred[16];
    __shared__ float sbc;

    const int b = blockIdx.x;
    const int v = threadIdx.x;

    const float x   = q[(size_t)b * Vn + v];
    const float vis = state[(size_t)b * SROW + v];

    float tempv = __expf(x - g_colM[v]) / g_colS[v] + 0.01f;
    tempv = (vis == 0.0f) ? tempv : 0.0f;   // exact mask: masked terms are exact zeros
    const float vp = x * Wv[v];

    float s1 = tempv, s2 = vp;
    #pragma unroll
    for (int off = 16; off >= 1; off >>= 1) {
        s1 += __shfl_xor_sync(0xffffffffu, s1, off);
        s2 += __shfl_xor_sync(0xffffffffu, s2, off);
    }
    const int lane = v & 31, w = v >> 5;
    if (lane == 0) { sred[w] = s1; sred[8 + w] = s2; }
    __syncthreads();
    if (v == 0) {
        float rs = 0.f, vv = 0.f;
        #pragma unroll
        for (int i = 0; i < 8; i++) { rs += sred[i]; vv += sred[8 + i]; }
        sbc = rs;
        value[b] = vv + bv[0];
    }
    __syncthreads();
    const float rowsum = sbc;

    float pol;
    if (rowsum == 0.0f) pol = (v == 0) ? 1.0f : 0.0f;   // onehot fallback
    else                pol = tempv / rowsum;
    policy[(size_t)b * Vn + v] = pol;
}

// ---------------------------------------------------------------------------
// launch
// ---------------------------------------------------------------------------
extern "C" void kernel_launch(void* const* d_in, const int* in_sizes, int n_in,
                              void* d_out, int out_size)
{
    const float* state = (const float*)d_in[0];
    const float* W1    = (const float*)d_in[1];
    const float* b_vis = (const float*)d_in[2];
    const float* w2    = (const float*)d_in[3];
    const float* Wv    = (const float*)d_in[4];
    const float* bv    = (const float*)d_in[5];

    float* out    = (float*)d_out;
    float* q      = out;                          // (B,V)
    float* policy = out + (size_t)Bn * Vn;        // (B,V)
    float* value  = out + (size_t)2 * Bn * Vn;    // (B,)

    k1_gemm<<<(Bn * Vn) / TM, 256>>>(state, W1, b_vis, w2, q);
    k2_colpart<<<64, 256>>>(q);
    k2_colcomb<<<1, 256>>>();
    k3_final<<<Bn, 256>>>(q, state, Wv, bv, policy, value);
}

// round 5
// speedup vs baseline: 2.5769x; 2.5769x over previous
#include <cuda_runtime.h>
#include <cstdint>

// ---------------------------------------------------------------- constants
#define Bn 4096
#define Vn 256
#define Hn 64
#define SROW (257 * 256)        // floats per batch element of `state`

#define GRID 148                // persistent: one CTA per SM
#define NTH  256                // 8 warps
#define NSTG 4                  // A pipeline stages

#define ASTRIDE 36              // A smem row stride (36 % 32 == 4 -> conflict-free A frags)
#define BSTRIDE 72              // B smem row stride (72 % 32 == 8 -> conflict-free B frags)
#define ASTF (256 * ASTRIDE)    // floats per A stage (9216)
// smem: A[4][9216] + B[256*72] + bias[64] + w2[64]
#define SMEM_FLOATS (NSTG * ASTF + 256 * BSTRIDE + 128)
#define SMEM_BYTES  (SMEM_FLOATS * 4)   // 221696

// ---------------------------------------------------------------- scratch
__device__ float g_pm[64 * Vn];
__device__ float g_ps[64 * Vn];
__device__ float g_colM[Vn];
__device__ float g_colS[Vn];

// ---------------------------------------------------------------- helpers
__device__ __forceinline__ uint32_t smem_u32(const void* p) {
    uint32_t a;
    asm("{ .reg .u64 t; cvta.to.shared.u64 t, %1; cvt.u32.u64 %0, t; }"
        : "=r"(a) : "l"(p));
    return a;
}
__device__ __forceinline__ void cpa16(uint32_t dst, const void* src) {
    asm volatile("cp.async.cg.shared.global [%0], [%1], 16;" :: "r"(dst), "l"(src));
}
#define CPA_COMMIT() asm volatile("cp.async.commit_group;" ::: "memory")

__device__ __forceinline__ uint32_t totf32(float x) {
    uint32_t r;
    asm("cvt.rna.tf32.f32 %0, %1;" : "=r"(r) : "f"(x));
    return r;
}
__device__ __forceinline__ void mma_tf32(float* d, const uint32_t* a,
                                         uint32_t b0, uint32_t b1) {
    asm volatile(
        "mma.sync.aligned.m16n8k8.row.col.f32.tf32.tf32.f32 "
        "{%0,%1,%2,%3}, {%4,%5,%6,%7}, {%8,%9}, {%0,%1,%2,%3};"
        : "+f"(d[0]), "+f"(d[1]), "+f"(d[2]), "+f"(d[3])
        : "r"(a[0]), "r"(a[1]), "r"(a[2]), "r"(a[3]), "r"(b0), "r"(b1));
}

// issue one 256-row x 32-k A chunk into stage `stg` via cp.async (one group)
__device__ __forceinline__ void issue_chunk(const float* __restrict__ state,
                                            uint32_t sA_u32, int blk, int c,
                                            int stg, int tid) {
    const int kq = tid & 7;         // 16B granule within 32-float k-chunk
    const int r0 = tid >> 3;        // 0..31 base row
    const float* src = state + (size_t)blk * SROW + (size_t)(r0 + 1) * 256
                     + c * 32 + kq * 4;
    uint32_t dst = sA_u32 + (uint32_t)(stg * ASTF + r0 * ASTRIDE + kq * 4) * 4u;
    #pragma unroll
    for (int i = 0; i < 8; i++) {   // rows r0 + 32*i
        cpa16(dst, src);
        dst += 32 * ASTRIDE * 4;
        src += 32 * 256;
    }
    CPA_COMMIT();
}

// ---------------------------------------------------------------- K1
// q[b*256+v] = sum_h relu( dist[b,v,:].W1[:,h] + vis[b,v]*b_vis[h] ) * w2[h]
// Persistent CTA; block = one batch b (256 rows). Warp tile: 32 rows x 64 h.
__global__ __launch_bounds__(NTH, 1)
void k1_gemm(const float* __restrict__ state, const float* __restrict__ W1,
             const float* __restrict__ b_vis, const float* __restrict__ w2,
             float* __restrict__ qout)
{
    extern __shared__ __align__(16) float sm[];
    float* sA    = sm;
    float* sB    = sm + NSTG * ASTF;
    float* sBias = sB + 256 * BSTRIDE;
    float* sW2   = sBias + 64;
    const uint32_t sA_u32 = smem_u32(sA);

    const int tid  = threadIdx.x;
    const int lane = tid & 31;
    const int warp = tid >> 5;
    const int bx   = blockIdx.x;

    const int nblk = (Bn - bx + GRID - 1) / GRID;
    const int NCC  = nblk * 8;               // chunks (8 per block)

    // prefetch chunk 0 while staging B
    issue_chunk(state, sA_u32, bx, 0, 0, tid);

    // stage B = W1 [256 k][64 h], tf32-rounded, stride 72
    #pragma unroll
    for (int i = 0; i < 16; i++) {
        const int idx  = tid + 256 * i;      // float4 index 0..4095
        const int kr   = idx >> 4;
        const int quad = idx & 15;
        const float4 v = ((const float4*)W1)[idx];
        float* dst = sB + kr * BSTRIDE + quad * 4;
        dst[0] = __uint_as_float(totf32(v.x));
        dst[1] = __uint_as_float(totf32(v.y));
        dst[2] = __uint_as_float(totf32(v.z));
        dst[3] = __uint_as_float(totf32(v.w));
    }
    if (tid < 64)        sBias[tid]     = b_vis[tid];
    else if (tid < 128)  sW2[tid - 64]  = w2[tid - 64];
    __syncthreads();

    float d[2][8][4];

    for (int cc = 0; cc < NCC; cc++) {
        const int blk = bx + (cc >> 3) * GRID;
        const int c   = cc & 7;

        if (cc + 1 < NCC) {
            const int cc1 = cc + 1;
            issue_chunk(state, sA_u32, bx + (cc1 >> 3) * GRID, cc1 & 7,
                        cc1 & 3, tid);
            asm volatile("cp.async.wait_group 1;" ::: "memory");
        } else {
            asm volatile("cp.async.wait_group 0;" ::: "memory");
        }
        __syncthreads();   // chunk cc visible everywhere; stage reuse safe (4 stages)

        if (c == 0) {
            #pragma unroll
            for (int g = 0; g < 2; g++)
                #pragma unroll
                for (int j = 0; j < 8; j++)
                    #pragma unroll
                    for (int e = 0; e < 4; e++) d[g][j][e] = 0.f;
        }

        const float* As = sA + (cc & 3) * ASTF;
        #pragma unroll
        for (int ks = 0; ks < 4; ks++) {
            const int k0 = ks * 8;
            const int kg = c * 32 + k0;

            uint32_t a[2][4];
            #pragma unroll
            for (int g = 0; g < 2; g++) {
                const float* ap = As + (warp * 32 + g * 16 + (lane >> 2)) * ASTRIDE
                                + k0 + (lane & 3);
                a[g][0] = totf32(ap[0]);
                a[g][1] = totf32(ap[8 * ASTRIDE]);
                a[g][2] = totf32(ap[4]);
                a[g][3] = totf32(ap[8 * ASTRIDE + 4]);
            }
            #pragma unroll
            for (int j = 0; j < 8; j++) {
                const float* bp = sB + (kg + (lane & 3)) * BSTRIDE
                                + j * 8 + (lane >> 2);
                const uint32_t b0 = __float_as_uint(bp[0]);
                const uint32_t b1 = __float_as_uint(bp[4 * BSTRIDE]);
                mma_tf32(d[0][j], a[0], b0, b1);
                mma_tf32(d[1][j], a[1], b0, b1);
            }
        }

        if (c == 7) {
            // fused epilogue: relu(acc + vis*bias)*w2, reduce over h
            #pragma unroll
            for (int g = 0; g < 2; g++) {
                #pragma unroll
                for (int half = 0; half < 2; half++) {
                    const int r = warp * 32 + g * 16 + (lane >> 2) + half * 8;
                    const float vis = __ldg(state + (size_t)blk * SROW + r);
                    float p = 0.f;
                    #pragma unroll
                    for (int j = 0; j < 8; j++) {
                        const int n = j * 8 + (lane & 3) * 2;
                        p += fmaxf(fmaf(vis, sBias[n],     d[g][j][half * 2]),     0.f) * sW2[n];
                        p += fmaxf(fmaf(vis, sBias[n + 1], d[g][j][half * 2 + 1]), 0.f) * sW2[n + 1];
                    }
                    p += __shfl_xor_sync(0xffffffffu, p, 1);
                    p += __shfl_xor_sync(0xffffffffu, p, 2);
                    if ((lane & 3) == 0)
                        qout[(size_t)blk * 256 + r] = p;
                }
            }
        }
    }
}

// ---------------------------------------------------------------- K2: column softmax stats
__global__ __launch_bounds__(256) void k2_colpart(const float* __restrict__ q)
{
    const int t  = threadIdx.x;
    const int r0 = blockIdx.x * 64;
    float m = -3.402823466e38f, s = 0.f;
    const float* p = q + (size_t)r0 * Vn + t;
    #pragma unroll 4
    for (int i = 0; i < 64; i++) {
        const float x  = p[(size_t)i * Vn];
        const float nm = fmaxf(m, x);
        s = s * __expf(m - nm) + __expf(x - nm);
        m = nm;
    }
    g_pm[blockIdx.x * Vn + t] = m;
    g_ps[blockIdx.x * Vn + t] = s;
}

__global__ __launch_bounds__(256) void k2_colcomb()
{
    const int t = threadIdx.x;
    float M = -3.402823466e38f;
    #pragma unroll 8
    for (int i = 0; i < 64; i++) M = fmaxf(M, g_pm[i * Vn + t]);
    float S = 0.f;
    #pragma unroll 8
    for (int i = 0; i < 64; i++) S += g_ps[i * Vn + t] * __expf(g_pm[i * Vn + t] - M);
    g_colM[t] = M;
    g_colS[t] = S;
}

// ---------------------------------------------------------------- K3: policy + value
__global__ __launch_bounds__(256) void k3_final(
    const float* __restrict__ q, const float* __restrict__ state,
    const float* __restrict__ Wv, const float* __restrict__ bv,
    float* __restrict__ policy, float* __restrict__ value)
{
    __shared__ float sred[16];
    __shared__ float sbc;

    const int b = blockIdx.x;
    const int v = threadIdx.x;

    const float x   = q[(size_t)b * Vn + v];
    const float vis = state[(size_t)b * SROW + v];

    float tempv = __expf(x - g_colM[v]) / g_colS[v] + 0.01f;
    tempv = (vis == 0.0f) ? tempv : 0.0f;   // masked terms exact zeros
    const float vp = x * Wv[v];

    float s1 = tempv, s2 = vp;
    #pragma unroll
    for (int off = 16; off >= 1; off >>= 1) {
        s1 += __shfl_xor_sync(0xffffffffu, s1, off);
        s2 += __shfl_xor_sync(0xffffffffu, s2, off);
    }
    const int lane = v & 31, w = v >> 5;
    if (lane == 0) { sred[w] = s1; sred[8 + w] = s2; }
    __syncthreads();
    if (v == 0) {
        float rs = 0.f, vv = 0.f;
        #pragma unroll
        for (int i = 0; i < 8; i++) { rs += sred[i]; vv += sred[8 + i]; }
        sbc = rs;
        value[b] = vv + bv[0];
    }
    __syncthreads();
    const float rowsum = sbc;

    float pol;
    if (rowsum == 0.0f) pol = (v == 0) ? 1.0f : 0.0f;
    else                pol = tempv / rowsum;
    policy[(size_t)b * Vn + v] = pol;
}

// ---------------------------------------------------------------- launch
extern "C" void kernel_launch(void* const* d_in, const int* in_sizes, int n_in,
                              void* d_out, int out_size)
{
    const float* state = (const float*)d_in[0];
    const float* W1    = (const float*)d_in[1];
    const float* b_vis = (const float*)d_in[2];
    const float* w2    = (const float*)d_in[3];
    const float* Wv    = (const float*)d_in[4];
    const float* bv    = (const float*)d_in[5];

    float* out    = (float*)d_out;
    float* q      = out;
    float* policy = out + (size_t)Bn * Vn;
    float* value  = out + (size_t)2 * Bn * Vn;

    cudaFuncSetAttribute(k1_gemm, cudaFuncAttributeMaxDynamicSharedMemorySize,
                         SMEM_BYTES);

    k1_gemm<<<GRID, NTH, SMEM_BYTES>>>(state, W1, b_vis, w2, q);
    k2_colpart<<<64, 256>>>(q);
    k2_colcomb<<<1, 256>>>();
    k3_final<<<Bn, 256>>>(q, state, Wv, bv, policy, value);
}